// round 9
// baseline (speedup 1.0000x reference)
#include <cuda_runtime.h>
#include <cuda_fp16.h>
#include <cstdint>

// ---------------------------------------------------------------------------
// EncoderByType (GB300, compute_103): FULLY FUSED 3-layer MLP.
// One CTA = 64 rows through all 3 layers; h1/h2 live in smem only.
// fp16 m16n8k16 mma.sync, cp.async 3-slot weight ring spanning layer
// boundaries, ldmatrix with XOR swizzle. 1 transpose + 3 cvt + 1 fused launch.
// ---------------------------------------------------------------------------

__device__ __half g_x [32014336];          // padded fp16 inputs (zero-init)
__device__ __half g_Wt[1409024];           // 9 weights, [N,K] fp16

// ------------------------- helpers -----------------------------------------
__device__ __forceinline__ uint32_t smem_u32(const void* p) {
    uint32_t a;
    asm("{ .reg .u64 t; cvta.to.shared.u64 t, %1; cvt.u32.u64 %0, t; }"
        : "=r"(a) : "l"(p));
    return a;
}
__device__ __forceinline__ float fast_sigmoid(float x) {
    float t;
    asm("tanh.approx.f32 %0, %1;" : "=f"(t) : "f"(0.5f * x));
    return fmaf(0.5f, t, 0.5f);
}
__device__ __forceinline__ uint32_t packh2(float lo, float hi) {
    __half2 h = __floats2half2_rn(lo, hi);
    return *reinterpret_cast<uint32_t*>(&h);
}
__device__ __forceinline__ void mma_fp16(float* d, const uint4& a,
                                         uint32_t b0, uint32_t b1) {
    asm volatile(
        "mma.sync.aligned.m16n8k16.row.col.f32.f16.f16.f32 "
        "{%0,%1,%2,%3}, {%4,%5,%6,%7}, {%8,%9}, {%0,%1,%2,%3};"
        : "+f"(d[0]), "+f"(d[1]), "+f"(d[2]), "+f"(d[3])
        : "r"(a.x), "r"(a.y), "r"(a.z), "r"(a.w), "r"(b0), "r"(b1));
}
__device__ __forceinline__ void ldsm4(uint4& d, uint32_t addr) {
    asm volatile(
        "ldmatrix.sync.aligned.m8n8.x4.shared.b16 {%0,%1,%2,%3}, [%4];"
        : "=r"(d.x), "=r"(d.y), "=r"(d.z), "=r"(d.w) : "r"(addr));
}
#define CP_ASYNC16(dst, src) \
    asm volatile("cp.async.cg.shared.global [%0], [%1], 16;" :: "r"(dst), "l"(src))
#define CP_COMMIT() asm volatile("cp.async.commit_group;" ::: "memory")
#define CP_WAIT(n)  asm volatile("cp.async.wait_group %0;" :: "n"(n) : "memory")

// ------------------------- weight transpose+convert ------------------------
struct TransArgs {
    const float* W[9];
    long long wtoff[9];
    int K[9];
    int N[9];
    int tbase[10];
};

__global__ void __launch_bounds__(256)
transpose_weights(TransArgs a) {
    int m = 0;
    while ((int)blockIdx.x >= a.tbase[m + 1]) m++;
    int t = blockIdx.x - a.tbase[m];
    int Km = a.K[m], Nm = a.N[m];
    int tilesN = Nm >> 5;
    int tk = t / tilesN, tn = t % tilesN;

    __shared__ float tile[32][33];
    int tx = threadIdx.x & 31, ty0 = threadIdx.x >> 5;
    const float* W = a.W[m];
#pragma unroll
    for (int i = 0; i < 4; i++) {
        int ty = ty0 + i * 8;
        tile[ty][tx] = W[(long long)(tk * 32 + ty) * Nm + tn * 32 + tx];
    }
    __syncthreads();
    __half* Wt = g_Wt + a.wtoff[m];
#pragma unroll
    for (int i = 0; i < 4; i++) {
        int ty = ty0 + i * 8;
        Wt[(long long)(tn * 32 + ty) * Km + tk * 32 + tx] = __float2half(tile[tx][ty]);
    }
}

// ------------------------- input convert (fp32 -> fp16) --------------------
__global__ void __launch_bounds__(128)
cvt_fp16(const float* __restrict__ s, __half* __restrict__ d, int n4) {
    int i = blockIdx.x * 128 + threadIdx.x;
    if (i < n4) {
        float4 v = ((const float4*)s)[i];
        uint2 o;
        o.x = packh2(v.x, v.y);
        o.y = packh2(v.z, v.w);
        ((uint2*)d)[i] = o;
    }
}

// ------------------------- fused MLP kernel --------------------------------
// 256 threads = 8 warps (2m x 4n), warp tile 32x64 within n-chunk 256.
// Smem: bufA 64KB (x then h2) | bufB 64KB (h1) | B ring 3 x 32KB = 224KB.
// h layout: row-major 512 cols fp16 (1024B rows), 16B chunks swizzled:
//   phys_chunk = (ck & ~7) | ((ck ^ row) & 7).
struct FArgs {
    const __half* x[3];
    const __half* Wt[9];     // [t*3+l]
    const float* bias[9];
    float* out;
    long long outb[3];
    int M[3];
    int K1[3];
    int tb[4];
};

__global__ void __launch_bounds__(256, 1)
mlp_fused(FArgs a)
{
    extern __shared__ char smem[];
    const int bx = blockIdx.x;
    const int t = (bx >= a.tb[1]) + (bx >= a.tb[2]);
    const long long bm = (long long)(bx - a.tb[t]) * 64;
    const int K1 = a.K1[t];
    const int tid = threadIdx.x, lane = tid & 31, wid = tid >> 5;
    const int warp_m = wid & 1, warp_n = wid >> 1;
    const uint32_t sb = smem_u32(smem);
    const uint32_t bufA = sb;
    const uint32_t bufB = sb + 65536;
    const uint32_t Bst  = sb + 131072;

    // ---- stage x tile (64 rows x K1 halfs) into bufA ----
    {
        const int CPR = K1 >> 3;                       // 16B chunks per row
        const int lg = (K1 == 64) ? 3 : (K1 == 128 ? 4 : 5);
        const int total = 64 * CPR;
        const __half* xs = a.x[t] + bm * K1;
        for (int idx = tid; idx < total; idx += 256) {
            int row = idx >> lg;
            int ck = idx & (CPR - 1);
            uint32_t dst = bufA +
                (uint32_t)(row * CPR + ((ck & ~7) | ((ck ^ row) & 7))) * 16u;
            CP_ASYNC16(dst, xs + (long long)row * K1 + ck * 8);
        }
    }
    CP_COMMIT();

    // ---- weight-slab prefetch state (flattened across layers) ----
    const __half* Wt0 = a.Wt[t * 3 + 0];
    const __half* Wt1 = a.Wt[t * 3 + 1];
    const __half* Wt2 = a.Wt[t * 3 + 2];
    const int KT1 = K1 >> 6;
    int lp = 0, ncp = 0, ktp = 0, pslot = 0;
    const int crow0 = tid >> 3, cchk = tid & 7;
    const uint32_t bdst0 = Bst + (uint32_t)crow0 * 128u +
                           ((uint32_t)((cchk ^ crow0) & 7) << 4);

    auto issueB = [&]() {
        if (lp < 3) {
            const __half* W = (lp == 0) ? Wt0 : (lp == 1 ? Wt1 : Wt2);
            const int Kl = (lp == 0) ? K1 : 512;
            const __half* src =
                W + (long long)(ncp * 256 + crow0) * Kl + ktp * 64 + cchk * 8;
            const uint32_t d0 = bdst0 + (uint32_t)pslot * 32768u;
            const long long step = 32ll * Kl;
#pragma unroll
            for (int i = 0; i < 8; i++)
                CP_ASYNC16(d0 + (uint32_t)i * 4096u, src + i * step);
            pslot = (pslot == 2) ? 0 : pslot + 1;
            const int ktn = (lp == 0) ? KT1 : 8;
            if (++ktp == ktn) {
                ktp = 0;
                const int nchn = (lp == 2) ? 1 : 2;
                if (++ncp == nchn) { ncp = 0; lp++; }
            }
        }
    };
    issueB(); CP_COMMIT();
    issueB(); CP_COMMIT();

    // ---- fragment addressing constants ----
    const int l15 = lane & 15, ahi = lane >> 4;
    const int brow_l = ((lane >> 4) << 3) + (lane & 7);
    const int bhi = (lane >> 3) & 1;
    const int g = lane >> 2, c = lane & 3;
    int slot = 0;

    for (int l = 0; l < 3; l++) {
        const uint32_t rd = (l == 1) ? bufB : bufA;
        const uint32_t wr = (l == 0) ? bufB : bufA;
        const int astr = (l == 0) ? (K1 * 2) : 1024;
        const int ktn = (l == 0) ? KT1 : 8;
        const int nchn = (l == 2) ? 1 : 2;
        for (int nc = 0; nc < nchn; nc++) {
            float acc[2][8][4];
#pragma unroll
            for (int i = 0; i < 2; i++)
#pragma unroll
                for (int j = 0; j < 8; j++)
#pragma unroll
                    for (int q = 0; q < 4; q++) acc[i][j][q] = 0.0f;

            for (int kt = 0; kt < ktn; kt++) {
                CP_WAIT(1);
                __syncthreads();
                issueB();
                CP_COMMIT();
                const uint32_t bS = Bst + (uint32_t)slot * 32768u;
                slot = (slot == 2) ? 0 : slot + 1;
#pragma unroll
                for (int s = 0; s < 4; s++) {
                    uint4 af[2];
#pragma unroll
                    for (int mt = 0; mt < 2; mt++) {
                        const int rowA = warp_m * 32 + mt * 16 + l15;
                        const int ck = kt * 8 + 2 * s + ahi;
                        ldsm4(af[mt], rd + (uint32_t)(rowA * astr) +
                              (uint32_t)(((ck & ~7) | ((ck ^ rowA) & 7)) << 4));
                    }
                    uint4 bf[4];
#pragma unroll
                    for (int ng = 0; ng < 4; ng++) {
                        const int rowB = warp_n * 64 + ng * 16 + brow_l;
                        const int ck = 2 * s + bhi;
                        ldsm4(bf[ng], bS + (uint32_t)(rowB * 128) +
                              (uint32_t)((ck ^ (lane & 7)) << 4));
                    }
#pragma unroll
                    for (int mt = 0; mt < 2; mt++)
#pragma unroll
                        for (int ng = 0; ng < 4; ng++) {
                            mma_fp16(acc[mt][2 * ng],     af[mt], bf[ng].x, bf[ng].y);
                            mma_fp16(acc[mt][2 * ng + 1], af[mt], bf[ng].z, bf[ng].w);
                        }
                }
            }

            // ---- epilogue: bias + sigmoid ----
            const float* bias = a.bias[t * 3 + l] + nc * 256 + warp_n * 64 + 2 * c;
            float2 bv[8];
#pragma unroll
            for (int np = 0; np < 8; np++) bv[np] = *(const float2*)(bias + np * 8);

            if (l < 2) {
#pragma unroll
                for (int mt = 0; mt < 2; mt++) {
                    const int r0 = warp_m * 32 + mt * 16 + g;
                    const int r1 = r0 + 8;
#pragma unroll
                    for (int np = 0; np < 8; np++) {
                        const int ckg = nc * 32 + warp_n * 8 + np;
                        float* d = acc[mt][np];
                        uint32_t p0 = packh2(fast_sigmoid(d[0] + bv[np].x),
                                             fast_sigmoid(d[1] + bv[np].y));
                        uint32_t p1 = packh2(fast_sigmoid(d[2] + bv[np].x),
                                             fast_sigmoid(d[3] + bv[np].y));
                        uint32_t a0 = wr + (uint32_t)(r0 * 1024) +
                            (uint32_t)(((ckg & ~7) | ((ckg ^ r0) & 7)) << 4) + 4 * c;
                        uint32_t a1 = wr + (uint32_t)(r1 * 1024) +
                            (uint32_t)(((ckg & ~7) | ((ckg ^ r1) & 7)) << 4) + 4 * c;
                        asm volatile("st.shared.b32 [%0], %1;" :: "r"(a0), "r"(p0) : "memory");
                        asm volatile("st.shared.b32 [%0], %1;" :: "r"(a1), "r"(p1) : "memory");
                    }
                }
            } else {
                const int M = a.M[t];
                float* out = a.out + a.outb[t] * 256;
#pragma unroll
                for (int mt = 0; mt < 2; mt++) {
                    const long long r0 = bm + warp_m * 32 + mt * 16 + g;
                    const long long r1 = r0 + 8;
#pragma unroll
                    for (int np = 0; np < 8; np++) {
                        const int n = warp_n * 64 + np * 8 + 2 * c;
                        float* d = acc[mt][np];
                        if (r0 < M)
                            *(float2*)(out + r0 * 256 + n) =
                                make_float2(fast_sigmoid(d[0] + bv[np].x),
                                            fast_sigmoid(d[1] + bv[np].y));
                        if (r1 < M)
                            *(float2*)(out + r1 * 256 + n) =
                                make_float2(fast_sigmoid(d[2] + bv[np].x),
                                            fast_sigmoid(d[3] + bv[np].y));
                    }
                }
            }
        }
        __syncthreads();   // h_out complete before next layer consumes it
    }
}

// ------------------------- host launcher -----------------------------------
extern "C" void kernel_launch(void* const* d_in, const int* in_sizes, int n_in,
                              void* d_out, int out_size)
{
    (void)n_in; (void)out_size;
    const int din[3] = {64, 128, 256};
    int n[3];
    for (int t = 0; t < 3; t++) n[t] = in_sizes[t] / din[t];

    int tiles[3], tb[4];
    tb[0] = 0;
    for (int t = 0; t < 3; t++) {
        tiles[t] = (n[t] + 63) / 64;
        tb[t + 1] = tb[t] + tiles[t];
    }
    long long padrows[3];
    for (int t = 0; t < 3; t++) padrows[t] = (long long)tiles[t] * 64;
    long long xoff[3] = {0, padrows[0] * din[0],
                         padrows[0] * din[0] + padrows[1] * din[1]};
    long long outbase[3] = {0, n[0], (long long)n[0] + n[1]};

    const int SMEM = 229376;   // 64 + 64 + 96 KB
    static int attr_done = 0;
    if (!attr_done) {
        cudaFuncSetAttribute(mlp_fused,
                             cudaFuncAttributeMaxDynamicSharedMemorySize, SMEM);
        attr_done = 1;
    }

    // ---- transpose + fp16-convert all weights ----
    TransArgs ta;
    long long woff[9];
    {
        long long w = 0;
        int tbt = 0;
        for (int t = 0; t < 3; t++) {
            int Ks[3] = {din[t], 512, 512};
            int Ns[3] = {512, 512, 256};
            for (int l = 0; l < 3; l++) {
                int idx = t * 3 + l;
                ta.W[idx] = (const float*)d_in[4 + 6 * t + 2 * l];
                ta.wtoff[idx] = w;
                woff[idx] = w;
                ta.K[idx] = Ks[l];
                ta.N[idx] = Ns[l];
                ta.tbase[idx] = tbt;
                tbt += (Ks[l] / 32) * (Ns[l] / 32);
                w += (long long)Ks[l] * Ns[l];
            }
        }
        ta.tbase[9] = tbt;
        transpose_weights<<<tbt, 256>>>(ta);
    }

    __half *xh, *wt;
    cudaGetSymbolAddress((void**)&xh, g_x);
    cudaGetSymbolAddress((void**)&wt, g_Wt);

    // ---- convert inputs to padded fp16 ----
    for (int t = 0; t < 3; t++) {
        int n4 = n[t] * din[t] / 4;
        cvt_fp16<<<(n4 + 127) / 128, 128>>>((const float*)d_in[t], xh + xoff[t], n4);
    }

    // ---- single fused launch ----
    FArgs a;
    for (int i = 0; i < 4; i++) a.tb[i] = tb[i];
    a.out = (float*)d_out;
    for (int t = 0; t < 3; t++) {
        a.x[t] = xh + xoff[t];
        a.M[t] = n[t];
        a.K1[t] = din[t];
        a.outb[t] = outbase[t];
        for (int l = 0; l < 3; l++) {
            a.Wt[t * 3 + l] = wt + woff[t * 3 + l];
            a.bias[t * 3 + l] = (const float*)d_in[5 + 6 * t + 2 * l];
        }
    }
    mlp_fused<<<tb[3], 256, SMEM>>>(a);
}

// round 10
// speedup vs baseline: 1.0738x; 1.0738x over previous
#include <cuda_runtime.h>
#include <cuda_fp16.h>
#include <cstdint>

// ---------------------------------------------------------------------------
// EncoderByType (GB300, compute_103): fp16 m16n8k16 mma.sync GEMM,
// cp.async 3-stage pipeline + FRAGMENT DOUBLE-BUFFERING, ldmatrix swizzled,
// 2 CTAs/SM (128 thr, 96KB). CTA 128x128x64, warp 64x64. fp16 activations,
// padded to 128-row tiles. 1 transpose + 1 cvt + 3 layer launches.
// ---------------------------------------------------------------------------

__device__ __half g_x [32014336];          // padded fp16 inputs
__device__ __half g_h1[240128ll * 512];
__device__ __half g_h2[240128ll * 512];
__device__ __half g_Wt[1409024];           // 9 weights, [N,K] fp16

// ------------------------- helpers -----------------------------------------
__device__ __forceinline__ uint32_t smem_u32(const void* p) {
    uint32_t a;
    asm("{ .reg .u64 t; cvta.to.shared.u64 t, %1; cvt.u32.u64 %0, t; }"
        : "=r"(a) : "l"(p));
    return a;
}
__device__ __forceinline__ float fast_sigmoid(float x) {
    float t;
    asm("tanh.approx.f32 %0, %1;" : "=f"(t) : "f"(0.5f * x));
    return fmaf(0.5f, t, 0.5f);
}
__device__ __forceinline__ uint32_t packh2(float lo, float hi) {
    __half2 h = __floats2half2_rn(lo, hi);
    return *reinterpret_cast<uint32_t*>(&h);
}
__device__ __forceinline__ void mma_fp16(float* d, const uint4& a,
                                         uint32_t b0, uint32_t b1) {
    asm volatile(
        "mma.sync.aligned.m16n8k16.row.col.f32.f16.f16.f32 "
        "{%0,%1,%2,%3}, {%4,%5,%6,%7}, {%8,%9}, {%0,%1,%2,%3};"
        : "+f"(d[0]), "+f"(d[1]), "+f"(d[2]), "+f"(d[3])
        : "r"(a.x), "r"(a.y), "r"(a.z), "r"(a.w), "r"(b0), "r"(b1));
}
__device__ __forceinline__ void ldsm4(uint4& d, uint32_t addr) {
    asm volatile(
        "ldmatrix.sync.aligned.m8n8.x4.shared.b16 {%0,%1,%2,%3}, [%4];"
        : "=r"(d.x), "=r"(d.y), "=r"(d.z), "=r"(d.w) : "r"(addr));
}
#define CP_ASYNC16(dst, src) \
    asm volatile("cp.async.cg.shared.global [%0], [%1], 16;" :: "r"(dst), "l"(src))
#define CP_COMMIT() asm volatile("cp.async.commit_group;" ::: "memory")
#define CP_WAIT(n)  asm volatile("cp.async.wait_group %0;" :: "n"(n) : "memory")

// ------------------------- weight transpose+convert ------------------------
struct TransArgs {
    const float* W[9];
    long long wtoff[9];
    int K[9];
    int N[9];
    int tbase[10];
};

__global__ void __launch_bounds__(256)
transpose_weights(TransArgs a) {
    int m = 0;
    while ((int)blockIdx.x >= a.tbase[m + 1]) m++;
    int t = blockIdx.x - a.tbase[m];
    int Km = a.K[m], Nm = a.N[m];
    int tilesN = Nm >> 5;
    int tk = t / tilesN, tn = t % tilesN;

    __shared__ float tile[32][33];
    int tx = threadIdx.x & 31, ty0 = threadIdx.x >> 5;
    const float* W = a.W[m];
#pragma unroll
    for (int i = 0; i < 4; i++) {
        int ty = ty0 + i * 8;
        tile[ty][tx] = W[(long long)(tk * 32 + ty) * Nm + tn * 32 + tx];
    }
    __syncthreads();
    __half* Wt = g_Wt + a.wtoff[m];
#pragma unroll
    for (int i = 0; i < 4; i++) {
        int ty = ty0 + i * 8;
        Wt[(long long)(tn * 32 + ty) * Km + tk * 32 + tx] = __float2half(tile[tx][ty]);
    }
}

// ------------------------- input convert (all 3 in one launch) -------------
__global__ void __launch_bounds__(256)
cvt_all(const float* s0, const float* s1, const float* s2,
        __half* d0, __half* d1, __half* d2, int c1, int c2, int c3)
{
    int i = blockIdx.x * 256 + threadIdx.x;
    if (i >= c3) return;
    const float* s;
    __half* d;
    int j;
    if (i < c1)      { s = s0; d = d0; j = i; }
    else if (i < c2) { s = s1; d = d1; j = i - c1; }
    else             { s = s2; d = d2; j = i - c2; }
    float4 v = ((const float4*)s)[j];
    uint2 o;
    o.x = packh2(v.x, v.y);
    o.y = packh2(v.z, v.w);
    ((uint2*)d)[j] = o;
}

// ------------------------- fused layer kernel ------------------------------
// Grid: (N/128, sum_tiles). CTA 128 threads = 4 warps (2m x 2n), warp 64x64.
// Smem: 3 stages x (A 16KB + B 16KB) = 96KB. BK = 64 halfs (128B rows),
// XOR swizzle: 16B chunk c stored at c ^ (row & 7).
struct LArgs {
    const __half* A[3];
    void* C[3];
    const float* bias[3];
    const __half* Wt[3];
    int M[3], K[3];
    int tb[4];
    int N;
};

template <bool CF32>
__global__ void __launch_bounds__(128)
mlp_layer(LArgs a)
{
    extern __shared__ char smem[];
    const int t = ((int)blockIdx.y >= a.tb[1]) + ((int)blockIdx.y >= a.tb[2]);
    const int K = a.K[t];
    const int N = a.N;
    const long long bm = (long long)((int)blockIdx.y - a.tb[t]) * 128;
    const int bn = blockIdx.x * 128;
    const __half* Ah = a.A[t];
    const __half* Wt = a.Wt[t];
    const int KT = K >> 6;

    const int tid = threadIdx.x;
    const int lane = tid & 31;
    const int wid = tid >> 5;
    const int warp_m = wid >> 1;
    const int warp_n = wid & 1;

    const uint32_t sb = smem_u32(smem);

    // ---- cp.async source/dst maps ----
    const int crow = tid >> 3;
    const int cchk = tid & 7;
    const __half* pA = Ah + (bm + crow) * (long long)K + cchk * 8;
    const __half* pB = Wt + (long long)(bn + crow) * K + cchk * 8;
    const uint32_t swz = (uint32_t)((cchk ^ (crow & 7)) * 16);
    const uint32_t dA = sb + crow * 128 + swz;
    const uint32_t dB = sb + 16384 + crow * 128 + swz;
    const long long rstep = 16ll * K;

    // ---- ldmatrix address bases ----
    const int l15 = lane & 15;
    const int ahi = lane >> 4;
    const uint32_t aX = (uint32_t)(lane & 7);
    const uint32_t aBase = sb + (uint32_t)(warp_m * 64 + l15) * 128;
    const int bn_l = warp_n * 64 + ((lane >> 4) << 3) + (lane & 7);
    const int bhi = (lane >> 3) & 1;
    const uint32_t bBase = sb + 16384 + (uint32_t)bn_l * 128;

    float acc[4][8][4];
#pragma unroll
    for (int i = 0; i < 4; i++)
#pragma unroll
        for (int j = 0; j < 8; j++)
#pragma unroll
            for (int q = 0; q < 4; q++) acc[i][j][q] = 0.0f;

    uint4 afr[2][4], bfr[2][4];

#define ISSUE(kt, slot)                                                      \
    do {                                                                     \
        const __half* sA_ = pA + (kt) * 64;                                  \
        const __half* sB_ = pB + (kt) * 64;                                  \
        uint32_t oA_ = dA + (slot) * 32768u;                                 \
        uint32_t oB_ = dB + (slot) * 32768u;                                 \
        _Pragma("unroll")                                                    \
        for (int i = 0; i < 8; i++)                                          \
            CP_ASYNC16(oA_ + i * 2048u, sA_ + i * rstep);                    \
        _Pragma("unroll")                                                    \
        for (int i = 0; i < 8; i++)                                          \
            CP_ASYNC16(oB_ + i * 2048u, sB_ + i * rstep);                    \
    } while (0)

#define LOAD_FRAGS(aS_, bS_, s_, pb_)                                        \
    do {                                                                     \
        _Pragma("unroll")                                                    \
        for (int mt = 0; mt < 4; mt++)                                       \
            ldsm4(afr[pb_][mt], (aS_) + mt * 2048u +                         \
                  ((((uint32_t)(2 * (s_) + ahi)) ^ aX) << 4));               \
        _Pragma("unroll")                                                    \
        for (int ng = 0; ng < 4; ng++)                                       \
            ldsm4(bfr[pb_][ng], (bS_) + ng * 2048u +                         \
                  ((((uint32_t)(2 * (s_) + bhi)) ^ aX) << 4));               \
    } while (0)

    // ---- prologue: fill 2 stages ----
    ISSUE(0, 0);
    CP_COMMIT();
    if (1 < KT) ISSUE(1, 1);
    CP_COMMIT();

    CP_WAIT(1);
    __syncthreads();
    uint32_t aS = aBase, bS = bBase;
    LOAD_FRAGS(aS, bS, 0, 0);

    int pf = 2;
    for (int kt = 0; kt < KT; kt++) {
        if (pf < KT) {
            int slot = pf - (pf / 3) * 3;
            ISSUE(pf, slot);
        }
        CP_COMMIT();
        pf++;

#pragma unroll
        for (int s = 0; s < 4; s++) {
            const int cb = s & 1;
            if (s < 3) LOAD_FRAGS(aS, bS, s + 1, cb ^ 1);
#pragma unroll
            for (int mt = 0; mt < 4; mt++)
#pragma unroll
                for (int ng = 0; ng < 4; ng++) {
                    mma_fp16(acc[mt][2 * ng],     afr[cb][mt], bfr[cb][ng].x, bfr[cb][ng].y);
                    mma_fp16(acc[mt][2 * ng + 1], afr[cb][mt], bfr[cb][ng].z, bfr[cb][ng].w);
                }
        }
        if (kt + 1 < KT) {
            CP_WAIT(1);
            __syncthreads();
            const int cur = (kt + 1) - ((kt + 1) / 3) * 3;
            aS = aBase + cur * 32768u;
            bS = bBase + cur * 32768u;
            LOAD_FRAGS(aS, bS, 0, 0);
        }
    }
#undef ISSUE
#undef LOAD_FRAGS

    // ---- epilogue: bias + sigmoid ----
    const float* bias = a.bias[t];
    const int M = a.M[t];
#pragma unroll
    for (int mt = 0; mt < 4; mt++) {
        long long r0 = bm + warp_m * 64 + mt * 16 + (lane >> 2);
        long long r1 = r0 + 8;
#pragma unroll
        for (int np = 0; np < 8; np++) {
            int n = bn + warp_n * 64 + np * 8 + 2 * (lane & 3);
            float2 bv = *(const float2*)(bias + n);
            float* d = acc[mt][np];
            float s0 = fast_sigmoid(d[0] + bv.x);
            float s1 = fast_sigmoid(d[1] + bv.y);
            float s2 = fast_sigmoid(d[2] + bv.x);
            float s3 = fast_sigmoid(d[3] + bv.y);
            if (CF32) {
                float* C = (float*)a.C[t];
                if (r0 < M) *(float2*)(C + r0 * N + n) = make_float2(s0, s1);
                if (r1 < M) *(float2*)(C + r1 * N + n) = make_float2(s2, s3);
            } else {
                __half* C = (__half*)a.C[t];
                *(uint32_t*)(C + r0 * N + n) = packh2(s0, s1);
                *(uint32_t*)(C + r1 * N + n) = packh2(s2, s3);
            }
        }
    }
}

// ------------------------- host launcher -----------------------------------
extern "C" void kernel_launch(void* const* d_in, const int* in_sizes, int n_in,
                              void* d_out, int out_size)
{
    (void)n_in; (void)out_size;
    const int din[3] = {64, 128, 256};
    int n[3];
    for (int t = 0; t < 3; t++) n[t] = in_sizes[t] / din[t];

    int tiles[3], tb[4];
    tb[0] = 0;
    for (int t = 0; t < 3; t++) {
        tiles[t] = (n[t] + 127) / 128;
        tb[t + 1] = tb[t] + tiles[t];
    }
    long long padrows[3] = {(long long)tiles[0] * 128, (long long)tiles[1] * 128,
                            (long long)tiles[2] * 128};
    long long hb[3] = {0, padrows[0], padrows[0] + padrows[1]};
    long long xoff[3] = {0, padrows[0] * din[0],
                         padrows[0] * din[0] + padrows[1] * din[1]};
    long long outbase[3] = {0, n[0], (long long)n[0] + n[1]};

    const int SMEM = 3 * 32768;   // 98304
    static int attr_done = 0;
    if (!attr_done) {
        cudaFuncSetAttribute(mlp_layer<false>,
                             cudaFuncAttributeMaxDynamicSharedMemorySize, SMEM);
        cudaFuncSetAttribute(mlp_layer<true>,
                             cudaFuncAttributeMaxDynamicSharedMemorySize, SMEM);
        attr_done = 1;
    }

    // ---- transpose + fp16-convert all weights ----
    TransArgs ta;
    long long woff[9];
    {
        long long w = 0;
        int tbt = 0;
        for (int t = 0; t < 3; t++) {
            int Ks[3] = {din[t], 512, 512};
            int Ns[3] = {512, 512, 256};
            for (int l = 0; l < 3; l++) {
                int idx = t * 3 + l;
                ta.W[idx] = (const float*)d_in[4 + 6 * t + 2 * l];
                ta.wtoff[idx] = w;
                woff[idx] = w;
                ta.K[idx] = Ks[l];
                ta.N[idx] = Ns[l];
                ta.tbase[idx] = tbt;
                tbt += (Ks[l] / 32) * (Ns[l] / 32);
                w += (long long)Ks[l] * Ns[l];
            }
        }
        ta.tbase[9] = tbt;
        transpose_weights<<<tbt, 256>>>(ta);
    }

    __half *xh, *h1, *h2, *wt;
    cudaGetSymbolAddress((void**)&xh, g_x);
    cudaGetSymbolAddress((void**)&h1, g_h1);
    cudaGetSymbolAddress((void**)&h2, g_h2);
    cudaGetSymbolAddress((void**)&wt, g_Wt);

    // ---- convert inputs to padded fp16 (one launch) ----
    {
        int c1 = n[0] * din[0] / 4;
        int c2 = c1 + n[1] * din[1] / 4;
        int c3 = c2 + n[2] * din[2] / 4;
        cvt_all<<<(c3 + 255) / 256, 256>>>(
            (const float*)d_in[0], (const float*)d_in[1], (const float*)d_in[2],
            xh + xoff[0], xh + xoff[1], xh + xoff[2], c1, c2, c3);
    }

    // ---- layer launches ----
    LArgs a;
    for (int i = 0; i < 4; i++) a.tb[i] = tb[i];

    a.N = 512;
    for (int t = 0; t < 3; t++) {
        a.A[t] = xh + xoff[t];
        a.C[t] = h1 + hb[t] * 512;
        a.bias[t] = (const float*)d_in[5 + 6 * t];
        a.Wt[t] = wt + woff[t * 3 + 0];
        a.M[t] = n[t];
        a.K[t] = din[t];
    }
    mlp_layer<false><<<dim3(4, tb[3]), 128, SMEM>>>(a);

    for (int t = 0; t < 3; t++) {
        a.A[t] = h1 + hb[t] * 512;
        a.C[t] = h2 + hb[t] * 512;
        a.bias[t] = (const float*)d_in[7 + 6 * t];
        a.Wt[t] = wt + woff[t * 3 + 1];
        a.M[t] = n[t];
        a.K[t] = 512;
    }
    mlp_layer<false><<<dim3(4, tb[3]), 128, SMEM>>>(a);

    a.N = 256;
    for (int t = 0; t < 3; t++) {
        a.A[t] = h2 + hb[t] * 512;
        a.C[t] = (float*)d_out + outbase[t] * 256;
        a.bias[t] = (const float*)d_in[9 + 6 * t];
        a.Wt[t] = wt + woff[t * 3 + 2];
        a.M[t] = n[t];
        a.K[t] = 512;
    }
    mlp_layer<true><<<dim3(2, tb[3]), 128, SMEM>>>(a);
}

// round 11
// speedup vs baseline: 1.1272x; 1.0497x over previous
#include <cuda_runtime.h>
#include <cuda_fp16.h>
#include <cstdint>

// ---------------------------------------------------------------------------
// EncoderByType (GB300, compute_103): fp16 m16n8k16 mma.sync GEMM.
// Round 11: 256 threads / 8 warps (warp tile 32x64), no fragment double
// buffering, <=128 regs -> 2 CTAs/SM = 16 warps/SM (TLP over ILP).
// CTA 128x128x64, 3-stage cp.async ring (96KB), ldmatrix XOR swizzle.
// fp16 activations padded to 128-row tiles. 1 transpose + 1 cvt + 3 layers.
// ---------------------------------------------------------------------------

__device__ __half g_x [32014336];          // padded fp16 inputs
__device__ __half g_h1[240128ll * 512];
__device__ __half g_h2[240128ll * 512];
__device__ __half g_Wt[1409024];           // 9 weights, [N,K] fp16

// ------------------------- helpers -----------------------------------------
__device__ __forceinline__ uint32_t smem_u32(const void* p) {
    uint32_t a;
    asm("{ .reg .u64 t; cvta.to.shared.u64 t, %1; cvt.u32.u64 %0, t; }"
        : "=r"(a) : "l"(p));
    return a;
}
__device__ __forceinline__ float fast_sigmoid(float x) {
    float t;
    asm("tanh.approx.f32 %0, %1;" : "=f"(t) : "f"(0.5f * x));
    return fmaf(0.5f, t, 0.5f);
}
__device__ __forceinline__ uint32_t packh2(float lo, float hi) {
    __half2 h = __floats2half2_rn(lo, hi);
    return *reinterpret_cast<uint32_t*>(&h);
}
__device__ __forceinline__ void mma_fp16(float* d, const uint4& a,
                                         uint32_t b0, uint32_t b1) {
    asm volatile(
        "mma.sync.aligned.m16n8k16.row.col.f32.f16.f16.f32 "
        "{%0,%1,%2,%3}, {%4,%5,%6,%7}, {%8,%9}, {%0,%1,%2,%3};"
        : "+f"(d[0]), "+f"(d[1]), "+f"(d[2]), "+f"(d[3])
        : "r"(a.x), "r"(a.y), "r"(a.z), "r"(a.w), "r"(b0), "r"(b1));
}
__device__ __forceinline__ void ldsm4(uint4& d, uint32_t addr) {
    asm volatile(
        "ldmatrix.sync.aligned.m8n8.x4.shared.b16 {%0,%1,%2,%3}, [%4];"
        : "=r"(d.x), "=r"(d.y), "=r"(d.z), "=r"(d.w) : "r"(addr));
}
#define CP_ASYNC16(dst, src) \
    asm volatile("cp.async.cg.shared.global [%0], [%1], 16;" :: "r"(dst), "l"(src))
#define CP_COMMIT() asm volatile("cp.async.commit_group;" ::: "memory")
#define CP_WAIT(n)  asm volatile("cp.async.wait_group %0;" :: "n"(n) : "memory")

// ------------------------- weight transpose+convert ------------------------
struct TransArgs {
    const float* W[9];
    long long wtoff[9];
    int K[9];
    int N[9];
    int tbase[10];
};

__global__ void __launch_bounds__(256)
transpose_weights(TransArgs a) {
    int m = 0;
    while ((int)blockIdx.x >= a.tbase[m + 1]) m++;
    int t = blockIdx.x - a.tbase[m];
    int Km = a.K[m], Nm = a.N[m];
    int tilesN = Nm >> 5;
    int tk = t / tilesN, tn = t % tilesN;

    __shared__ float tile[32][33];
    int tx = threadIdx.x & 31, ty0 = threadIdx.x >> 5;
    const float* W = a.W[m];
#pragma unroll
    for (int i = 0; i < 4; i++) {
        int ty = ty0 + i * 8;
        tile[ty][tx] = W[(long long)(tk * 32 + ty) * Nm + tn * 32 + tx];
    }
    __syncthreads();
    __half* Wt = g_Wt + a.wtoff[m];
#pragma unroll
    for (int i = 0; i < 4; i++) {
        int ty = ty0 + i * 8;
        Wt[(long long)(tn * 32 + ty) * Km + tk * 32 + tx] = __float2half(tile[tx][ty]);
    }
}

// ------------------------- input convert (all 3 in one launch) -------------
__global__ void __launch_bounds__(256)
cvt_all(const float* s0, const float* s1, const float* s2,
        __half* d0, __half* d1, __half* d2, int c1, int c2, int c3)
{
    int i = blockIdx.x * 256 + threadIdx.x;
    if (i >= c3) return;
    const float* s;
    __half* d;
    int j;
    if (i < c1)      { s = s0; d = d0; j = i; }
    else if (i < c2) { s = s1; d = d1; j = i - c1; }
    else             { s = s2; d = d2; j = i - c2; }
    float4 v = ((const float4*)s)[j];
    uint2 o;
    o.x = packh2(v.x, v.y);
    o.y = packh2(v.z, v.w);
    ((uint2*)d)[j] = o;
}

// ------------------------- fused layer kernel ------------------------------
// Grid: (N/128, sum_tiles). CTA 256 threads = 8 warps (4m x 2n), warp 32x64.
// Smem: 3 stages x (A 16KB + B 16KB) = 96KB. BK = 64 halfs (128B rows),
// XOR swizzle: 16B chunk c stored at c ^ (row & 7).
struct LArgs {
    const __half* A[3];
    void* C[3];
    const float* bias[3];
    const __half* Wt[3];
    int M[3], K[3];
    int tb[4];
    int N;
};

template <bool CF32>
__global__ void __launch_bounds__(256, 2)
mlp_layer(LArgs a)
{
    extern __shared__ char smem[];
    const int t = ((int)blockIdx.y >= a.tb[1]) + ((int)blockIdx.y >= a.tb[2]);
    const int K = a.K[t];
    const int N = a.N;
    const long long bm = (long long)((int)blockIdx.y - a.tb[t]) * 128;
    const int bn = blockIdx.x * 128;
    const __half* Ah = a.A[t];
    const __half* Wt = a.Wt[t];
    const int KT = K >> 6;

    const int tid = threadIdx.x;
    const int lane = tid & 31;
    const int wid = tid >> 5;
    const int warp_m = wid & 3;     // 4 m-warps of 32 rows
    const int warp_n = wid >> 2;    // 2 n-warps of 64 cols

    const uint32_t sb = smem_u32(smem);

    // ---- cp.async maps: 256 thr x 8 chunks (4 A rows-strided, 4 B) ----
    const int crow = tid >> 3;          // 0..31 (+ i*32)
    const int cchk = tid & 7;
    const __half* pA = Ah + (bm + crow) * (long long)K + cchk * 8;
    const __half* pB = Wt + (long long)(bn + crow) * K + cchk * 8;
    const uint32_t swz = (uint32_t)((cchk ^ (crow & 7)) * 16);
    const uint32_t dA = sb + crow * 128 + swz;
    const uint32_t dB = sb + 16384 + crow * 128 + swz;
    const long long rstep = 32ll * K;   // halfs per 32 rows

    // ---- ldmatrix address bases ----
    const int l15 = lane & 15;
    const int ahi = lane >> 4;
    const uint32_t aX = (uint32_t)(lane & 7);
    const uint32_t aBase = sb + (uint32_t)(warp_m * 32 + l15) * 128;
    const int bn_l = warp_n * 64 + ((lane >> 4) << 3) + (lane & 7);
    const int bhi = (lane >> 3) & 1;
    const uint32_t bBase = sb + 16384 + (uint32_t)bn_l * 128;

    float acc[2][8][4];
#pragma unroll
    for (int i = 0; i < 2; i++)
#pragma unroll
        for (int j = 0; j < 8; j++)
#pragma unroll
            for (int q = 0; q < 4; q++) acc[i][j][q] = 0.0f;

#define ISSUE(kt, slot)                                                      \
    do {                                                                     \
        const __half* sA_ = pA + (kt) * 64;                                  \
        const __half* sB_ = pB + (kt) * 64;                                  \
        uint32_t oA_ = dA + (slot) * 32768u;                                 \
        uint32_t oB_ = dB + (slot) * 32768u;                                 \
        _Pragma("unroll")                                                    \
        for (int i = 0; i < 4; i++)                                          \
            CP_ASYNC16(oA_ + i * 4096u, sA_ + i * rstep);                    \
        _Pragma("unroll")                                                    \
        for (int i = 0; i < 4; i++)                                          \
            CP_ASYNC16(oB_ + i * 4096u, sB_ + i * rstep);                    \
    } while (0)

    // ---- prologue: fill 2 stages ----
    ISSUE(0, 0);
    CP_COMMIT();
    if (1 < KT) ISSUE(1, 1);
    CP_COMMIT();

    int pf = 2;
    for (int kt = 0; kt < KT; kt++) {
        CP_WAIT(1);
        __syncthreads();
        if (pf < KT) {
            int slot = pf - (pf / 3) * 3;
            ISSUE(pf, slot);
        }
        CP_COMMIT();
        pf++;

        const int cur = kt - (kt / 3) * 3;
        const uint32_t aS = aBase + cur * 32768u;
        const uint32_t bS = bBase + cur * 32768u;
#pragma unroll
        for (int s = 0; s < 4; s++) {
            uint4 af[2];
#pragma unroll
            for (int mt = 0; mt < 2; mt++)
                ldsm4(af[mt], aS + mt * 2048u + ((((uint32_t)(2 * s + ahi)) ^ aX) << 4));
            uint4 bf[4];
#pragma unroll
            for (int ng = 0; ng < 4; ng++)
                ldsm4(bf[ng], bS + ng * 2048u + ((((uint32_t)(2 * s + bhi)) ^ aX) << 4));
#pragma unroll
            for (int mt = 0; mt < 2; mt++)
#pragma unroll
                for (int ng = 0; ng < 4; ng++) {
                    mma_fp16(acc[mt][2 * ng],     af[mt], bf[ng].x, bf[ng].y);
                    mma_fp16(acc[mt][2 * ng + 1], af[mt], bf[ng].z, bf[ng].w);
                }
        }
    }
#undef ISSUE

    // ---- epilogue: bias + sigmoid ----
    const float* bias = a.bias[t];
    const int M = a.M[t];
#pragma unroll
    for (int mt = 0; mt < 2; mt++) {
        long long r0 = bm + warp_m * 32 + mt * 16 + (lane >> 2);
        long long r1 = r0 + 8;
#pragma unroll
        for (int np = 0; np < 8; np++) {
            int n = bn + warp_n * 64 + np * 8 + 2 * (lane & 3);
            float2 bv = *(const float2*)(bias + n);
            float* d = acc[mt][np];
            float s0 = fast_sigmoid(d[0] + bv.x);
            float s1 = fast_sigmoid(d[1] + bv.y);
            float s2 = fast_sigmoid(d[2] + bv.x);
            float s3 = fast_sigmoid(d[3] + bv.y);
            if (CF32) {
                float* C = (float*)a.C[t];
                if (r0 < M) *(float2*)(C + r0 * N + n) = make_float2(s0, s1);
                if (r1 < M) *(float2*)(C + r1 * N + n) = make_float2(s2, s3);
            } else {
                __half* C = (__half*)a.C[t];
                *(uint32_t*)(C + r0 * N + n) = packh2(s0, s1);
                *(uint32_t*)(C + r1 * N + n) = packh2(s2, s3);
            }
        }
    }
}

// ------------------------- host launcher -----------------------------------
extern "C" void kernel_launch(void* const* d_in, const int* in_sizes, int n_in,
                              void* d_out, int out_size)
{
    (void)n_in; (void)out_size;
    const int din[3] = {64, 128, 256};
    int n[3];
    for (int t = 0; t < 3; t++) n[t] = in_sizes[t] / din[t];

    int tiles[3], tb[4];
    tb[0] = 0;
    for (int t = 0; t < 3; t++) {
        tiles[t] = (n[t] + 127) / 128;
        tb[t + 1] = tb[t] + tiles[t];
    }
    long long padrows[3] = {(long long)tiles[0] * 128, (long long)tiles[1] * 128,
                            (long long)tiles[2] * 128};
    long long hb[3] = {0, padrows[0], padrows[0] + padrows[1]};
    long long xoff[3] = {0, padrows[0] * din[0],
                         padrows[0] * din[0] + padrows[1] * din[1]};
    long long outbase[3] = {0, n[0], (long long)n[0] + n[1]};

    const int SMEM = 3 * 32768;   // 98304
    static int attr_done = 0;
    if (!attr_done) {
        cudaFuncSetAttribute(mlp_layer<false>,
                             cudaFuncAttributeMaxDynamicSharedMemorySize, SMEM);
        cudaFuncSetAttribute(mlp_layer<true>,
                             cudaFuncAttributeMaxDynamicSharedMemorySize, SMEM);
        attr_done = 1;
    }

    // ---- transpose + fp16-convert all weights ----
    TransArgs ta;
    long long woff[9];
    {
        long long w = 0;
        int tbt = 0;
        for (int t = 0; t < 3; t++) {
            int Ks[3] = {din[t], 512, 512};
            int Ns[3] = {512, 512, 256};
            for (int l = 0; l < 3; l++) {
                int idx = t * 3 + l;
                ta.W[idx] = (const float*)d_in[4 + 6 * t + 2 * l];
                ta.wtoff[idx] = w;
                woff[idx] = w;
                ta.K[idx] = Ks[l];
                ta.N[idx] = Ns[l];
                ta.tbase[idx] = tbt;
                tbt += (Ks[l] / 32) * (Ns[l] / 32);
                w += (long long)Ks[l] * Ns[l];
            }
        }
        ta.tbase[9] = tbt;
        transpose_weights<<<tbt, 256>>>(ta);
    }

    __half *xh, *h1, *h2, *wt;
    cudaGetSymbolAddress((void**)&xh, g_x);
    cudaGetSymbolAddress((void**)&h1, g_h1);
    cudaGetSymbolAddress((void**)&h2, g_h2);
    cudaGetSymbolAddress((void**)&wt, g_Wt);

    // ---- convert inputs to padded fp16 (one launch) ----
    {
        int c1 = n[0] * din[0] / 4;
        int c2 = c1 + n[1] * din[1] / 4;
        int c3 = c2 + n[2] * din[2] / 4;
        cvt_all<<<(c3 + 255) / 256, 256>>>(
            (const float*)d_in[0], (const float*)d_in[1], (const float*)d_in[2],
            xh + xoff[0], xh + xoff[1], xh + xoff[2], c1, c2, c3);
    }

    // ---- layer launches ----
    LArgs a;
    for (int i = 0; i < 4; i++) a.tb[i] = tb[i];

    a.N = 512;
    for (int t = 0; t < 3; t++) {
        a.A[t] = xh + xoff[t];
        a.C[t] = h1 + hb[t] * 512;
        a.bias[t] = (const float*)d_in[5 + 6 * t];
        a.Wt[t] = wt + woff[t * 3 + 0];
        a.M[t] = n[t];
        a.K[t] = din[t];
    }
    mlp_layer<false><<<dim3(4, tb[3]), 256, SMEM>>>(a);

    for (int t = 0; t < 3; t++) {
        a.A[t] = h1 + hb[t] * 512;
        a.C[t] = h2 + hb[t] * 512;
        a.bias[t] = (const float*)d_in[7 + 6 * t];
        a.Wt[t] = wt + woff[t * 3 + 1];
        a.M[t] = n[t];
        a.K[t] = 512;
    }
    mlp_layer<false><<<dim3(4, tb[3]), 256, SMEM>>>(a);

    a.N = 256;
    for (int t = 0; t < 3; t++) {
        a.A[t] = h2 + hb[t] * 512;
        a.C[t] = (float*)d_out + outbase[t] * 256;
        a.bias[t] = (const float*)d_in[9 + 6 * t];
        a.Wt[t] = wt + woff[t * 3 + 2];
        a.M[t] = n[t];
        a.K[t] = 512;
    }
    mlp_layer<true><<<dim3(2, tb[3]), 256, SMEM>>>(a);
}